// round 1
// baseline (speedup 1.0000x reference)
#include <cuda_runtime.h>

namespace {

constexpr int Bn = 256;
constexpr int Dn = 256;
constexpr int Nn = 1024;
constexpr float EPS_NORM = 1e-12f;
constexpr float EPS_DIV  = 1e-5f;

// Block-wide sum over 1024 threads (32 warps). All threads must call.
__device__ __forceinline__ float block_reduce(float val, float* red) {
#pragma unroll
    for (int o = 16; o; o >>= 1) val += __shfl_down_sync(0xffffffffu, val, o);
    const int lane = threadIdx.x & 31;
    const int wid  = threadIdx.x >> 5;
    if (lane == 0) red[wid] = val;
    __syncthreads();
    if (wid == 0) {
        val = red[lane];
#pragma unroll
        for (int o = 16; o; o >>= 1) val += __shfl_down_sync(0xffffffffu, val, o);
        if (lane == 0) red[0] = val;
    }
    __syncthreads();
    float r = red[0];
    __syncthreads();   // protect red[] for the next call
    return r;
}

__global__ __launch_bounds__(1024, 1) void svpn_kernel(
    const float* __restrict__ x,       // (B, D, N)
    const float* __restrict__ weight,  // (D,)
    float* __restrict__ out)           // (B, D*N)
{
    __shared__ float v[Dn];    // current right vector (unnormalized scale ok at init)
    __shared__ float v1[Dn];   // component-1 right vector
    __shared__ float zb[Dn];   // z = A^T u scratch
    __shared__ float u[Nn];    // current left vector (ends as u2)
    __shared__ float u1[Nn];   // component-1 left vector
    __shared__ float red[32];
    __shared__ float sS[2];    // spectral values s1, s2

    const int tid = threadIdx.x;
    const int b   = blockIdx.x;
    const float* xb = x + (size_t)b * Dn * Nn;

    if (tid < Dn) v[tid] = weight[tid];
    __syncthreads();

    for (int sv = 0; sv < 2; ++sv) {
        const float s1 = (sv == 1) ? sS[0] : 0.f;
        for (int it = 0; it < 3; ++it) {
            // ---- deflation dot (v1 . v) before u-pass ----
            float dvv = 0.f;
            if (sv == 1) {
                float p = (tid < Dn) ? v1[tid] * v[tid] : 0.f;
                dvv = block_reduce(p, red);
            }

            // ---- u-pass: w[n] = sum_d x[d,n] * v[d]   (thread per n, coalesced) ----
            float acc = 0.f;
            const float* xp = xb + tid;  // n = tid
#pragma unroll 8
            for (int d = 0; d < Dn; ++d)
                acc = fmaf(xp[(size_t)d * Nn], v[d], acc);
            if (sv == 1) acc -= s1 * dvv * u1[tid];

            float ss  = block_reduce(acc * acc, red);
            float inv = 1.f / fmaxf(sqrtf(ss), EPS_NORM);
            u[tid] = acc * inv;
            __syncthreads();

            // ---- deflation dot (u1 . u) before v-pass ----
            float duu = 0.f;
            if (sv == 1) duu = block_reduce(u1[tid] * u[tid], red);

            // ---- v-pass: z[d] = sum_n x[d,n] * u[n]   (warp per row, float4) ----
            {
                const int wid  = tid >> 5;
                const int lane = tid & 31;
                const float4* u4 = reinterpret_cast<const float4*>(u);
#pragma unroll
                for (int r = 0; r < 8; ++r) {
                    const int d = wid * 8 + r;
                    const float4* row =
                        reinterpret_cast<const float4*>(xb + (size_t)d * Nn);
                    float racc = 0.f;
#pragma unroll
                    for (int j = 0; j < 8; ++j) {
                        const int i = lane + 32 * j;
                        float4 xv = row[i];
                        float4 uv = u4[i];
                        racc += xv.x * uv.x + xv.y * uv.y + xv.z * uv.z + xv.w * uv.w;
                    }
#pragma unroll
                    for (int o = 16; o; o >>= 1)
                        racc += __shfl_down_sync(0xffffffffu, racc, o);
                    if (lane == 0) zb[d] = racc;
                }
            }
            __syncthreads();

            // ---- normalize z -> v ;  s = ||z|| on last iteration ----
            float zv = 0.f;
            if (tid < Dn) {
                zv = zb[tid];
                if (sv == 1) zv -= s1 * duu * v1[tid];
            }
            float zz   = block_reduce(zv * zv, red);
            float nrm  = sqrtf(zz);
            float zinv = 1.f / fmaxf(nrm, EPS_NORM);
            if (tid < Dn) v[tid] = zv * zinv;
            if (tid == 0 && it == 2) sS[sv] = nrm;
            __syncthreads();
        }
        if (sv == 0) {
            u1[tid] = u[tid];
            if (tid < Dn) {
                v1[tid] = v[tid];
                v[tid]  = weight[tid];   // reset for second component
            }
            __syncthreads();
        }
    }

    // ---- final fused output:
    // out[d,n] = c*x[d,n] + (sqrt(s1)-s1*c)*u1[n]*v1[d] + (sqrt(s2)-s2*c)*u2[n]*v2[d]
    const float s1f = sS[0], s2f = sS[1];
    const float c  = 1.f / (sqrtf(s2f) + EPS_DIV);
    const float c1 = sqrtf(s1f) - s1f * c;
    const float c2 = sqrtf(s2f) - s2f * c;

    const float4* x4  = reinterpret_cast<const float4*>(xb);
    float4*       o4  = reinterpret_cast<float4*>(out + (size_t)b * Dn * Nn);
    const float4* u14 = reinterpret_cast<const float4*>(u1);
    const float4* u24 = reinterpret_cast<const float4*>(u);  // u holds u2

    constexpr int TOT4 = Dn * Nn / 4;       // 65536
#pragma unroll 4
    for (int idx = tid; idx < TOT4; idx += 1024) {
        const int d   = idx >> 8;           // Nn/4 = 256 float4 per row
        const int col = idx & 255;
        const float a1 = c1 * v1[d];
        const float a2 = c2 * v[d];        // v holds v2
        const float4 xv = x4[idx];
        const float4 uA = u14[col];
        const float4 uB = u24[col];
        float4 o;
        o.x = fmaf(c, xv.x, fmaf(a1, uA.x, a2 * uB.x));
        o.y = fmaf(c, xv.y, fmaf(a1, uA.y, a2 * uB.y));
        o.z = fmaf(c, xv.z, fmaf(a1, uA.z, a2 * uB.z));
        o.w = fmaf(c, xv.w, fmaf(a1, uA.w, a2 * uB.w));
        o4[idx] = o;
    }
}

}  // namespace

extern "C" void kernel_launch(void* const* d_in, const int* in_sizes, int n_in,
                              void* d_out, int out_size) {
    const float* x = (const float*)d_in[0];
    const float* w = (const float*)d_in[1];
    // Defensive: ensure x is the big tensor, weight the small one.
    if (n_in >= 2 && in_sizes[0] < in_sizes[1]) {
        const float* t = x; x = w; w = t;
    }
    svpn_kernel<<<Bn, 1024>>>(x, w, (float*)d_out);
}

// round 2
// speedup vs baseline: 1.0059x; 1.0059x over previous
#include <cuda_runtime.h>

namespace {

constexpr int Bn = 256;
constexpr int Dn = 256;
constexpr int Nn = 1024;
constexpr float EPS_NORM = 1e-12f;
constexpr float EPS_DIV  = 1e-5f;

// Block-wide sum over 1024 threads (32 warps). All threads must call.
__device__ __forceinline__ float block_reduce(float val, float* red) {
#pragma unroll
    for (int o = 16; o; o >>= 1) val += __shfl_down_sync(0xffffffffu, val, o);
    const int lane = threadIdx.x & 31;
    const int wid  = threadIdx.x >> 5;
    if (lane == 0) red[wid] = val;
    __syncthreads();
    if (wid == 0) {
        val = red[lane];
#pragma unroll
        for (int o = 16; o; o >>= 1) val += __shfl_down_sync(0xffffffffu, val, o);
        if (lane == 0) red[0] = val;
    }
    __syncthreads();
    float r = red[0];
    __syncthreads();   // protect red[] for the next call
    return r;
}

__global__ __launch_bounds__(1024, 1) void svpn_kernel(
    const float* __restrict__ x,       // (B, D, N)
    const float* __restrict__ weight,  // (D,)
    float* __restrict__ out)           // (B, D*N)
{
    __shared__ float v[Dn];    // current right vector (unnormalized scale ok at init)
    __shared__ float v1[Dn];   // component-1 right vector
    __shared__ float zb[Dn];   // z = A^T u scratch
    __shared__ float u[Nn];    // current left vector (ends as u2)
    __shared__ float u1[Nn];   // component-1 left vector
    __shared__ float red[32];
    __shared__ float sS[2];    // spectral values s1, s2

    const int tid = threadIdx.x;
    const int b   = blockIdx.x;
    const float* xb = x + (size_t)b * Dn * Nn;

    if (tid < Dn) v[tid] = weight[tid];
    __syncthreads();

    for (int sv = 0; sv < 2; ++sv) {
        const float s1 = (sv == 1) ? sS[0] : 0.f;
        for (int it = 0; it < 3; ++it) {
            // ---- deflation dot (v1 . v) before u-pass ----
            float dvv = 0.f;
            if (sv == 1) {
                float p = (tid < Dn) ? v1[tid] * v[tid] : 0.f;
                dvv = block_reduce(p, red);
            }

            // ---- u-pass: w[n] = sum_d x[d,n] * v[d]   (thread per n, coalesced) ----
            float acc = 0.f;
            const float* xp = xb + tid;  // n = tid
#pragma unroll 8
            for (int d = 0; d < Dn; ++d)
                acc = fmaf(xp[(size_t)d * Nn], v[d], acc);
            if (sv == 1) acc -= s1 * dvv * u1[tid];

            float ss  = block_reduce(acc * acc, red);
            float inv = 1.f / fmaxf(sqrtf(ss), EPS_NORM);
            u[tid] = acc * inv;
            __syncthreads();

            // ---- deflation dot (u1 . u) before v-pass ----
            float duu = 0.f;
            if (sv == 1) duu = block_reduce(u1[tid] * u[tid], red);

            // ---- v-pass: z[d] = sum_n x[d,n] * u[n]   (warp per row, float4) ----
            {
                const int wid  = tid >> 5;
                const int lane = tid & 31;
                const float4* u4 = reinterpret_cast<const float4*>(u);
#pragma unroll
                for (int r = 0; r < 8; ++r) {
                    const int d = wid * 8 + r;
                    const float4* row =
                        reinterpret_cast<const float4*>(xb + (size_t)d * Nn);
                    float racc = 0.f;
#pragma unroll
                    for (int j = 0; j < 8; ++j) {
                        const int i = lane + 32 * j;
                        float4 xv = row[i];
                        float4 uv = u4[i];
                        racc += xv.x * uv.x + xv.y * uv.y + xv.z * uv.z + xv.w * uv.w;
                    }
#pragma unroll
                    for (int o = 16; o; o >>= 1)
                        racc += __shfl_down_sync(0xffffffffu, racc, o);
                    if (lane == 0) zb[d] = racc;
                }
            }
            __syncthreads();

            // ---- normalize z -> v ;  s = ||z|| on last iteration ----
            float zv = 0.f;
            if (tid < Dn) {
                zv = zb[tid];
                if (sv == 1) zv -= s1 * duu * v1[tid];
            }
            float zz   = block_reduce(zv * zv, red);
            float nrm  = sqrtf(zz);
            float zinv = 1.f / fmaxf(nrm, EPS_NORM);
            if (tid < Dn) v[tid] = zv * zinv;
            if (tid == 0 && it == 2) sS[sv] = nrm;
            __syncthreads();
        }
        if (sv == 0) {
            u1[tid] = u[tid];
            if (tid < Dn) {
                v1[tid] = v[tid];
                v[tid]  = weight[tid];   // reset for second component
            }
            __syncthreads();
        }
    }

    // ---- final fused output:
    // out[d,n] = c*x[d,n] + (sqrt(s1)-s1*c)*u1[n]*v1[d] + (sqrt(s2)-s2*c)*u2[n]*v2[d]
    const float s1f = sS[0], s2f = sS[1];
    const float c  = 1.f / (sqrtf(s2f) + EPS_DIV);
    const float c1 = sqrtf(s1f) - s1f * c;
    const float c2 = sqrtf(s2f) - s2f * c;

    const float4* x4  = reinterpret_cast<const float4*>(xb);
    float4*       o4  = reinterpret_cast<float4*>(out + (size_t)b * Dn * Nn);
    const float4* u14 = reinterpret_cast<const float4*>(u1);
    const float4* u24 = reinterpret_cast<const float4*>(u);  // u holds u2

    constexpr int TOT4 = Dn * Nn / 4;       // 65536
#pragma unroll 4
    for (int idx = tid; idx < TOT4; idx += 1024) {
        const int d   = idx >> 8;           // Nn/4 = 256 float4 per row
        const int col = idx & 255;
        const float a1 = c1 * v1[d];
        const float a2 = c2 * v[d];        // v holds v2
        const float4 xv = x4[idx];
        const float4 uA = u14[col];
        const float4 uB = u24[col];
        float4 o;
        o.x = fmaf(c, xv.x, fmaf(a1, uA.x, a2 * uB.x));
        o.y = fmaf(c, xv.y, fmaf(a1, uA.y, a2 * uB.y));
        o.z = fmaf(c, xv.z, fmaf(a1, uA.z, a2 * uB.z));
        o.w = fmaf(c, xv.w, fmaf(a1, uA.w, a2 * uB.w));
        o4[idx] = o;
    }
}

}  // namespace

extern "C" void kernel_launch(void* const* d_in, const int* in_sizes, int n_in,
                              void* d_out, int out_size) {
    const float* x = (const float*)d_in[0];
    const float* w = (const float*)d_in[1];
    // Defensive: ensure x is the big tensor, weight the small one.
    if (n_in >= 2 && in_sizes[0] < in_sizes[1]) {
        const float* t = x; x = w; w = t;
    }
    svpn_kernel<<<Bn, 1024>>>(x, w, (float*)d_out);
}

// round 3
// speedup vs baseline: 1.0090x; 1.0031x over previous
#include <cuda_runtime.h>

namespace {

constexpr int Bn = 256;
constexpr int Dn = 256;
constexpr int Nn = 1024;
constexpr float EPS_NORM = 1e-12f;
constexpr float EPS_DIV  = 1e-5f;

// Block-wide sum over 1024 threads (32 warps). All threads must call.
__device__ __forceinline__ float block_reduce(float val, float* red) {
#pragma unroll
    for (int o = 16; o; o >>= 1) val += __shfl_down_sync(0xffffffffu, val, o);
    const int lane = threadIdx.x & 31;
    const int wid  = threadIdx.x >> 5;
    if (lane == 0) red[wid] = val;
    __syncthreads();
    if (wid == 0) {
        val = red[lane];
#pragma unroll
        for (int o = 16; o; o >>= 1) val += __shfl_down_sync(0xffffffffu, val, o);
        if (lane == 0) red[0] = val;
    }
    __syncthreads();
    float r = red[0];
    __syncthreads();   // protect red[] for the next call
    return r;
}

__global__ __launch_bounds__(1024, 1) void svpn_kernel(
    const float* __restrict__ x,       // (B, D, N)
    const float* __restrict__ weight,  // (D,)
    float* __restrict__ out)           // (B, D*N)
{
    __shared__ float v[Dn];    // current right vector (unnormalized scale ok at init)
    __shared__ float v1[Dn];   // component-1 right vector
    __shared__ float zb[Dn];   // z = A^T u scratch
    __shared__ float u[Nn];    // current left vector (ends as u2)
    __shared__ float u1[Nn];   // component-1 left vector
    __shared__ float red[32];
    __shared__ float sS[2];    // spectral values s1, s2

    const int tid = threadIdx.x;
    const int b   = blockIdx.x;
    const float* xb = x + (size_t)b * Dn * Nn;

    if (tid < Dn) v[tid] = weight[tid];
    __syncthreads();

    for (int sv = 0; sv < 2; ++sv) {
        const float s1 = (sv == 1) ? sS[0] : 0.f;
        for (int it = 0; it < 3; ++it) {
            // ---- deflation dot (v1 . v) before u-pass ----
            float dvv = 0.f;
            if (sv == 1) {
                float p = (tid < Dn) ? v1[tid] * v[tid] : 0.f;
                dvv = block_reduce(p, red);
            }

            // ---- u-pass: w[n] = sum_d x[d,n] * v[d]   (thread per n, coalesced) ----
            float acc = 0.f;
            const float* xp = xb + tid;  // n = tid
#pragma unroll 8
            for (int d = 0; d < Dn; ++d)
                acc = fmaf(xp[(size_t)d * Nn], v[d], acc);
            if (sv == 1) acc -= s1 * dvv * u1[tid];

            float ss  = block_reduce(acc * acc, red);
            float inv = 1.f / fmaxf(sqrtf(ss), EPS_NORM);
            u[tid] = acc * inv;
            __syncthreads();

            // ---- deflation dot (u1 . u) before v-pass ----
            float duu = 0.f;
            if (sv == 1) duu = block_reduce(u1[tid] * u[tid], red);

            // ---- v-pass: z[d] = sum_n x[d,n] * u[n]   (warp per row, float4) ----
            {
                const int wid  = tid >> 5;
                const int lane = tid & 31;
                const float4* u4 = reinterpret_cast<const float4*>(u);
#pragma unroll
                for (int r = 0; r < 8; ++r) {
                    const int d = wid * 8 + r;
                    const float4* row =
                        reinterpret_cast<const float4*>(xb + (size_t)d * Nn);
                    float racc = 0.f;
#pragma unroll
                    for (int j = 0; j < 8; ++j) {
                        const int i = lane + 32 * j;
                        float4 xv = row[i];
                        float4 uv = u4[i];
                        racc += xv.x * uv.x + xv.y * uv.y + xv.z * uv.z + xv.w * uv.w;
                    }
#pragma unroll
                    for (int o = 16; o; o >>= 1)
                        racc += __shfl_down_sync(0xffffffffu, racc, o);
                    if (lane == 0) zb[d] = racc;
                }
            }
            __syncthreads();

            // ---- normalize z -> v ;  s = ||z|| on last iteration ----
            float zv = 0.f;
            if (tid < Dn) {
                zv = zb[tid];
                if (sv == 1) zv -= s1 * duu * v1[tid];
            }
            float zz   = block_reduce(zv * zv, red);
            float nrm  = sqrtf(zz);
            float zinv = 1.f / fmaxf(nrm, EPS_NORM);
            if (tid < Dn) v[tid] = zv * zinv;
            if (tid == 0 && it == 2) sS[sv] = nrm;
            __syncthreads();
        }
        if (sv == 0) {
            u1[tid] = u[tid];
            if (tid < Dn) {
                v1[tid] = v[tid];
                v[tid]  = weight[tid];   // reset for second component
            }
            __syncthreads();
        }
    }

    // ---- final fused output:
    // out[d,n] = c*x[d,n] + (sqrt(s1)-s1*c)*u1[n]*v1[d] + (sqrt(s2)-s2*c)*u2[n]*v2[d]
    const float s1f = sS[0], s2f = sS[1];
    const float c  = 1.f / (sqrtf(s2f) + EPS_DIV);
    const float c1 = sqrtf(s1f) - s1f * c;
    const float c2 = sqrtf(s2f) - s2f * c;

    const float4* x4  = reinterpret_cast<const float4*>(xb);
    float4*       o4  = reinterpret_cast<float4*>(out + (size_t)b * Dn * Nn);
    const float4* u14 = reinterpret_cast<const float4*>(u1);
    const float4* u24 = reinterpret_cast<const float4*>(u);  // u holds u2

    constexpr int TOT4 = Dn * Nn / 4;       // 65536
#pragma unroll 4
    for (int idx = tid; idx < TOT4; idx += 1024) {
        const int d   = idx >> 8;           // Nn/4 = 256 float4 per row
        const int col = idx & 255;
        const float a1 = c1 * v1[d];
        const float a2 = c2 * v[d];        // v holds v2
        const float4 xv = x4[idx];
        const float4 uA = u14[col];
        const float4 uB = u24[col];
        float4 o;
        o.x = fmaf(c, xv.x, fmaf(a1, uA.x, a2 * uB.x));
        o.y = fmaf(c, xv.y, fmaf(a1, uA.y, a2 * uB.y));
        o.z = fmaf(c, xv.z, fmaf(a1, uA.z, a2 * uB.z));
        o.w = fmaf(c, xv.w, fmaf(a1, uA.w, a2 * uB.w));
        o4[idx] = o;
    }
}

}  // namespace

extern "C" void kernel_launch(void* const* d_in, const int* in_sizes, int n_in,
                              void* d_out, int out_size) {
    const float* x = (const float*)d_in[0];
    const float* w = (const float*)d_in[1];
    // Defensive: ensure x is the big tensor, weight the small one.
    if (n_in >= 2 && in_sizes[0] < in_sizes[1]) {
        const float* t = x; x = w; w = t;
    }
    svpn_kernel<<<Bn, 1024>>>(x, w, (float*)d_out);
}